// round 9
// baseline (speedup 1.0000x reference)
#include <cuda_runtime.h>
#include <cstdint>

// out[m,n] = a * (h[m,:] @ B2[:,n]) + (1-a) * h[m,n]
// B2[k, head*64+d] = W[head,k,d]; a = clip(res_alpha,0,1).
// (softmax row-sums are exactly 1 -> attention block is identity; adj unused)
//
// bf16 2-split x 3-term emulated-fp32 GEMM on mma.m16n8k16:
//   x = hi + lo (hi = fp32 truncated to bf16), D = Ahi*Bhi + Ahi*Blo + Alo*Bhi
// R8: both A and B live in smem as bf16x2 hi/lo in MMA-fragment slot order:
// mainloop per k16 = 24x LDS.64 + 48x MMA, zero split ALU between LDS and MMA.
// A is split once at tile-load (LDG prefetch one chunk ahead), B pre-split in prep.

#define K_DIM   256
#define NDIM    256
#define BM      128
#define BN      128
#define KC      32
#define NCHUNK  (K_DIM / KC)
#define ST      36                      // smem row stride in u32: 16 hi + 16 lo + 4 pad
#define STAGE_U ((BM + BN) * ST)        // 9216 u32 per stage
#define THREADS 256

__device__ uint32_t g_Bh[NDIM * K_DIM / 2];   // [n][pair-slot] bf16x2 hi (fragment order)
__device__ uint32_t g_Bl[NDIM * K_DIM / 2];

// pack two fp32 -> bf16x2 hi (truncation) + bf16x2 lo (residual)
__device__ __forceinline__ void split_pack(float f0, float f1,
                                           uint32_t& hi, uint32_t& lo) {
    uint32_t u0 = __float_as_uint(f0);
    uint32_t u1 = __float_as_uint(f1);
    hi = __byte_perm(u0, u1, 0x7632);
    float r0 = f0 - __uint_as_float(u0 & 0xFFFF0000u);
    float r1 = f1 - __uint_as_float(u1 & 0xFFFF0000u);
    lo = __byte_perm(__float_as_uint(r0), __float_as_uint(r1), 0x7632);
}

// prep: transpose W -> [n][k], split, store pairs in fragment-slot order:
// pair p: chunk=p>>4, k16=(p>>3)&1, q=p&7, slot = 2*(q&3) + (q>>2)
__global__ void prep_Bt(const float* __restrict__ W) {
    int idx = blockIdx.x * blockDim.x + threadIdx.x;   // 32768
    int n = idx >> 7;
    int p = idx & 127;
    int head = n >> 6, d = n & 63;
    float f0 = W[((size_t)head * K_DIM + 2 * p) * 64 + d];
    float f1 = W[((size_t)head * K_DIM + 2 * p + 1) * 64 + d];
    uint32_t hi, lo;
    split_pack(f0, f1, hi, lo);
    int q = p & 7;
    int slot = (p >> 4) * 16 + (((p >> 3) & 1) * 8) + 2 * (q & 3) + (q >> 2);
    g_Bh[n * 128 + slot] = hi;
    g_Bl[n * 128 + slot] = lo;
}

__device__ __forceinline__ void mma_bf16(float d[4],
                                         uint32_t a0, uint32_t a1, uint32_t a2, uint32_t a3,
                                         uint32_t b0, uint32_t b1) {
    asm volatile(
        "mma.sync.aligned.m16n8k16.row.col.f32.bf16.bf16.f32 "
        "{%0,%1,%2,%3}, {%4,%5,%6,%7}, {%8,%9}, {%0,%1,%2,%3};"
        : "+f"(d[0]), "+f"(d[1]), "+f"(d[2]), "+f"(d[3])
        : "r"(a0), "r"(a1), "r"(a2), "r"(a3), "r"(b0), "r"(b1));
}

__device__ __forceinline__ void cp16(uint32_t saddr, const void* g) {
    asm volatile("cp.async.cg.shared.global [%0], [%1], 16;"
                 :: "r"(saddr), "l"(g) : "memory");
}
__device__ __forceinline__ uint2 lds64(uint32_t saddr) {
    uint2 v;
    asm volatile("ld.shared.v2.u32 {%0,%1}, [%2];" : "=r"(v.x), "=r"(v.y) : "r"(saddr));
    return v;
}
__device__ __forceinline__ void sts128(uint32_t saddr, uint32_t x, uint32_t y,
                                       uint32_t z, uint32_t w) {
    asm volatile("st.shared.v4.u32 [%0], {%1,%2,%3,%4};"
                 :: "r"(saddr), "r"(x), "r"(y), "r"(z), "r"(w) : "memory");
}

__global__ __launch_bounds__(THREADS, 2)
void gat_mma_gemm(const float* __restrict__ h,
                  const float* __restrict__ res_alpha,
                  float* __restrict__ out)
{
    extern __shared__ uint32_t su[];
    const uint32_t smem_b = (uint32_t)__cvta_generic_to_shared(su);

    const int tid = threadIdx.x;
    const int wid = tid >> 5;
    const int lid = tid & 31;
    const int grp = lid >> 2;
    const int tig = lid & 3;

    const int m0 = blockIdx.y * BM;
    const int n0 = blockIdx.x * BN;
    const int wm = (wid & 3) * 32;
    const int wn = (wid >> 2) * 64;

    float acc[2][8][4];
    #pragma unroll
    for (int mt = 0; mt < 2; ++mt)
        #pragma unroll
        for (int nt = 0; nt < 8; ++nt)
            #pragma unroll
            for (int q = 0; q < 4; ++q)
                acc[mt][nt][q] = 0.0f;

    // ---- per-thread A unit mapping: 2 units, each = 1 row-half of a k16 group
    // uid = tid*2+u: row = uid>>2, k16 = (uid>>1)&1, halfp = uid&1
    // unit loads float4 @ (c*32 + k16*16 + halfp*4) and @ +8  -> pairs P,P+1,P+4,P+5
    float4 pf[2][2];

    auto issueA = [&](int c) {
        #pragma unroll
        for (int u = 0; u < 2; ++u) {
            int uid = tid * 2 + u;
            int row = uid >> 2;
            int kb = c * KC + ((uid >> 1) & 1) * 16 + (uid & 1) * 4;
            const float* src = &h[(size_t)(m0 + row) * K_DIM + kb];
            pf[u][0] = *reinterpret_cast<const float4*>(src);
            pf[u][1] = *reinterpret_cast<const float4*>(src + 8);
        }
    };
    auto stsA = [&](int s) {
        #pragma unroll
        for (int u = 0; u < 2; ++u) {
            int uid = tid * 2 + u;
            int row = uid >> 2;
            int k16 = (uid >> 1) & 1;
            int halfp = uid & 1;
            uint32_t h0, l0, h1, l1, h4, l4, h5, l5;
            split_pack(pf[u][0].x, pf[u][0].y, h0, l0);
            split_pack(pf[u][0].z, pf[u][0].w, h1, l1);
            split_pack(pf[u][1].x, pf[u][1].y, h4, l4);
            split_pack(pf[u][1].z, pf[u][1].w, h5, l5);
            // slots: [p%4*2 + p/4] -> this unit covers 4 consecutive slots
            uint32_t off = smem_b + (uint32_t)(s * STAGE_U + row * ST + k16 * 8 + halfp * 4) * 4u;
            sts128(off, h0, h4, h1, h5);
            sts128(off + 16 * 4, l0, l4, l1, l5);
        }
    };
    auto issueB = [&](int c, int s) {
        int row = tid >> 1;
        int hb = (tid & 1) * 8;
        uint32_t dst = smem_b + (uint32_t)(s * STAGE_U + (BM + row) * ST + hb) * 4u;
        const uint32_t* sh = &g_Bh[(n0 + row) * 128 + c * 16 + hb];
        const uint32_t* sl = &g_Bl[(n0 + row) * 128 + c * 16 + hb];
        cp16(dst, sh);
        cp16(dst + 16, sh + 4);
        cp16(dst + 16 * 4, sl);
        cp16(dst + 16 * 4 + 16, sl + 4);
        asm volatile("cp.async.commit_group;" ::: "memory");
    };

    // prologue: fill stage 0
    issueA(0);
    stsA(0);
    issueB(0, 0);

    for (int c = 0; c < NCHUNK; ++c) {
        const int s = c & 1;
        asm volatile("cp.async.wait_group 0;" ::: "memory");
        __syncthreads();   // stage s ready; all warps done with s^1

        if (c + 1 < NCHUNK) {
            issueA(c + 1);          // LDG in flight under compute
            issueB(c + 1, s ^ 1);   // cp.async in flight under compute
        }

        const uint32_t abase = smem_b + (uint32_t)(s * STAGE_U) * 4u;
        const uint32_t bbase = abase + (uint32_t)(BM * ST) * 4u;

        #pragma unroll
        for (int k16 = 0; k16 < 2; ++k16) {
            const uint32_t ks = (uint32_t)(k16 * 8 + 2 * tig) * 4u;

            // A fragments: hi and lo, both M tiles
            uint32_t ah[2][4], al[2][4];
            #pragma unroll
            for (int mt = 0; mt < 2; ++mt) {
                uint32_t r0 = abase + (uint32_t)((wm + mt * 16 + grp) * ST) * 4u + ks;
                uint32_t r1 = r0 + (uint32_t)(8 * ST) * 4u;
                uint2 hL = lds64(r0);            // (a0, a2)
                uint2 hH = lds64(r1);            // (a1, a3)
                uint2 lL = lds64(r0 + 64);
                uint2 lH = lds64(r1 + 64);
                ah[mt][0] = hL.x; ah[mt][1] = hH.x; ah[mt][2] = hL.y; ah[mt][3] = hH.y;
                al[mt][0] = lL.x; al[mt][1] = lH.x; al[mt][2] = lL.y; al[mt][3] = lH.y;
            }

            #pragma unroll
            for (int half = 0; half < 2; ++half) {
                uint2 bh[4], bl[4];
                #pragma unroll
                for (int q = 0; q < 4; ++q) {
                    uint32_t nb = bbase +
                        (uint32_t)((wn + (half * 4 + q) * 8 + grp) * ST) * 4u + ks;
                    bh[q] = lds64(nb);           // (b0, b1)
                    bl[q] = lds64(nb + 64);
                }
                // term-major: acc-reuse distance 8
                #pragma unroll
                for (int q = 0; q < 4; ++q)
                    #pragma unroll
                    for (int mt = 0; mt < 2; ++mt)
                        mma_bf16(acc[mt][half * 4 + q],
                                 ah[mt][0], ah[mt][1], ah[mt][2], ah[mt][3],
                                 bh[q].x, bh[q].y);
                #pragma unroll
                for (int q = 0; q < 4; ++q)
                    #pragma unroll
                    for (int mt = 0; mt < 2; ++mt)
                        mma_bf16(acc[mt][half * 4 + q],
                                 ah[mt][0], ah[mt][1], ah[mt][2], ah[mt][3],
                                 bl[q].x, bl[q].y);
                #pragma unroll
                for (int q = 0; q < 4; ++q)
                    #pragma unroll
                    for (int mt = 0; mt < 2; ++mt)
                        mma_bf16(acc[mt][half * 4 + q],
                                 al[mt][0], al[mt][1], al[mt][2], al[mt][3],
                                 bh[q].x, bh[q].y);
            }
        }

        if (c + 1 < NCHUNK)
            stsA(s ^ 1);   // all warps past this iter's sync -> s^1 free to overwrite
    }

    // ---- epilogue: out = a*acc + (1-a)*h ----
    float a = res_alpha[0];
    a = fminf(fmaxf(a, 0.0f), 1.0f);
    const float ra = 1.0f - a;

    #pragma unroll
    for (int mt = 0; mt < 2; ++mt) {
        const int r0 = m0 + wm + mt * 16 + grp;
        #pragma unroll
        for (int nt = 0; nt < 8; ++nt) {
            const int cc = n0 + wn + nt * 8 + 2 * tig;
            {
                size_t gi = (size_t)r0 * NDIM + cc;
                float2 hv = *reinterpret_cast<const float2*>(&h[gi]);
                float2 o;
                o.x = fmaf(a, acc[mt][nt][0], ra * hv.x);
                o.y = fmaf(a, acc[mt][nt][1], ra * hv.y);
                *reinterpret_cast<float2*>(&out[gi]) = o;
            }
            {
                size_t gi = (size_t)(r0 + 8) * NDIM + cc;
                float2 hv = *reinterpret_cast<const float2*>(&h[gi]);
                float2 o;
                o.x = fmaf(a, acc[mt][nt][2], ra * hv.x);
                o.y = fmaf(a, acc[mt][nt][3], ra * hv.y);
                *reinterpret_cast<float2*>(&out[gi]) = o;
            }
        }
    }
}

extern "C" void kernel_launch(void* const* d_in, const int* in_sizes, int n_in,
                              void* d_out, int out_size) {
    const float* h         = (const float*)d_in[0];   // [8, 2048, 256]
    // d_in[1] = adj (unused)
    const float* W         = (const float*)d_in[2];   // [4, 256, 64]
    const float* res_alpha = (const float*)d_in[3];
    float* out             = (float*)d_out;

    const int M = in_sizes[0] / K_DIM;                // 16384

    prep_Bt<<<(NDIM * K_DIM / 2) / 256, 256>>>(W);

    const int smem_bytes = 2 * STAGE_U * 4;           // 73728
    cudaFuncSetAttribute(gat_mma_gemm,
                         cudaFuncAttributeMaxDynamicSharedMemorySize, smem_bytes);
    dim3 grid(NDIM / BN, M / BM);                     // (2, 128)
    gat_mma_gemm<<<grid, THREADS, smem_bytes>>>(h, res_alpha, out);
}

// round 10
// speedup vs baseline: 1.2242x; 1.2242x over previous
#include <cuda_runtime.h>
#include <cstdint>

// out[m,n] = a * (h[m,:] @ B2[:,n]) + (1-a) * h[m,n]
// B2[k, head*64+d] = W[head,k,d]; a = clip(res_alpha,0,1).
// (softmax row-sums are exactly 1 -> attention block is identity; adj unused)
//
// bf16 2-split x 3-term emulated-fp32 GEMM on mma.m16n8k16:
//   x = hi + lo (hi = fp32 truncated to bf16), D = Ahi*Bhi + Ahi*Blo + Alo*Bhi
// R10: ldmatrix.x4 fragment feed from pre-split smem planes.
//   smem layout: [row][k] bf16, 64B data + 16B pad = 80B stride
//   (80*r mod 128 distinct for r=0..7 -> conflict-free ldmatrix phases).
//   Mainloop per k16 per warp: 12x LDSM.x4 + 48x HMMA, no split ALU.

#define K_DIM   256
#define NDIM    256
#define BM      128
#define BN      128
#define KC      32
#define NCHUNK  (K_DIM / KC)
#define RSTRIDE 80                       // bytes per smem row (64 data + 16 pad)
#define PLANE   (128 * RSTRIDE)          // 10240 B per plane (128 rows)
#define STAGE_B (4 * PLANE)              // Ahi, Alo, Bhi, Blo = 40960 B
#define THREADS 256

__device__ uint32_t g_Bh[NDIM * K_DIM / 2];   // [n][pair] bf16x2 hi, natural k order
__device__ uint32_t g_Bl[NDIM * K_DIM / 2];

// pack two fp32 -> bf16x2 hi (truncation) + bf16x2 lo (residual)
__device__ __forceinline__ void split_pack(float f0, float f1,
                                           uint32_t& hi, uint32_t& lo) {
    uint32_t u0 = __float_as_uint(f0);
    uint32_t u1 = __float_as_uint(f1);
    hi = __byte_perm(u0, u1, 0x7632);
    float r0 = f0 - __uint_as_float(u0 & 0xFFFF0000u);
    float r1 = f1 - __uint_as_float(u1 & 0xFFFF0000u);
    lo = __byte_perm(__float_as_uint(r0), __float_as_uint(r1), 0x7632);
}

__global__ void prep_Bt(const float* __restrict__ W) {
    int idx = blockIdx.x * blockDim.x + threadIdx.x;   // 32768
    int n = idx >> 7;
    int p = idx & 127;                  // k-pair
    int head = n >> 6, d = n & 63;
    float f0 = W[((size_t)head * K_DIM + 2 * p) * 64 + d];
    float f1 = W[((size_t)head * K_DIM + 2 * p + 1) * 64 + d];
    uint32_t hi, lo;
    split_pack(f0, f1, hi, lo);
    g_Bh[n * 128 + p] = hi;
    g_Bl[n * 128 + p] = lo;
}

__device__ __forceinline__ void mma_bf16(float d[4],
                                         uint32_t a0, uint32_t a1, uint32_t a2, uint32_t a3,
                                         uint32_t b0, uint32_t b1) {
    asm volatile(
        "mma.sync.aligned.m16n8k16.row.col.f32.bf16.bf16.f32 "
        "{%0,%1,%2,%3}, {%4,%5,%6,%7}, {%8,%9}, {%0,%1,%2,%3};"
        : "+f"(d[0]), "+f"(d[1]), "+f"(d[2]), "+f"(d[3])
        : "r"(a0), "r"(a1), "r"(a2), "r"(a3), "r"(b0), "r"(b1));
}

__device__ __forceinline__ uint4 ldsm4(uint32_t saddr) {
    uint4 v;
    asm volatile("ldmatrix.sync.aligned.m8n8.x4.shared.b16 {%0,%1,%2,%3}, [%4];"
                 : "=r"(v.x), "=r"(v.y), "=r"(v.z), "=r"(v.w) : "r"(saddr));
    return v;
}
__device__ __forceinline__ void cp16(uint32_t saddr, const void* g) {
    asm volatile("cp.async.cg.shared.global [%0], [%1], 16;"
                 :: "r"(saddr), "l"(g) : "memory");
}
__device__ __forceinline__ void sts128(uint32_t saddr, uint32_t x, uint32_t y,
                                       uint32_t z, uint32_t w) {
    asm volatile("st.shared.v4.u32 [%0], {%1,%2,%3,%4};"
                 :: "r"(saddr), "r"(x), "r"(y), "r"(z), "r"(w) : "memory");
}

__global__ __launch_bounds__(THREADS, 2)
void gat_mma_gemm(const float* __restrict__ h,
                  const float* __restrict__ res_alpha,
                  float* __restrict__ out)
{
    extern __shared__ uint32_t su[];
    const uint32_t smem_b = (uint32_t)__cvta_generic_to_shared(su);

    const int tid = threadIdx.x;
    const int wid = tid >> 5;
    const int lid = tid & 31;
    const int grp = lid >> 2;
    const int tig = lid & 3;

    const int m0 = blockIdx.y * BM;
    const int n0 = blockIdx.x * BN;
    const int wm = (wid & 3) * 32;
    const int wn = (wid >> 2) * 64;

    // ldmatrix per-lane address components (byte offsets within a plane)
    const uint32_t a_lane = (uint32_t)((wm + (lid & 15)) * RSTRIDE + ((lid >> 4) & 1) * 16);
    const uint32_t b_lane = (uint32_t)((wn + (lid & 7) + ((lid >> 4) & 1) * 8) * RSTRIDE +
                                      ((lid >> 3) & 1) * 16);

    // loader mapping: row = tid>>1, kh = tid&1 (16 k-values = 32 bytes)
    const int ld_row = tid >> 1;
    const int ld_kh  = tid & 1;

    float acc[2][8][4];
    #pragma unroll
    for (int mt = 0; mt < 2; ++mt)
        #pragma unroll
        for (int nt = 0; nt < 8; ++nt)
            #pragma unroll
            for (int q = 0; q < 4; ++q)
                acc[mt][nt][q] = 0.0f;

    float4 pf[4];                        // A prefetch: 16 fp32

    auto ldgA = [&](int c) {
        const float* src = &h[(size_t)(m0 + ld_row) * K_DIM + c * KC + ld_kh * 16];
        pf[0] = *reinterpret_cast<const float4*>(src);
        pf[1] = *reinterpret_cast<const float4*>(src + 4);
        pf[2] = *reinterpret_cast<const float4*>(src + 8);
        pf[3] = *reinterpret_cast<const float4*>(src + 12);
    };
    auto stsA = [&](int s) {
        uint32_t hp[8], lp[8];
        split_pack(pf[0].x, pf[0].y, hp[0], lp[0]);
        split_pack(pf[0].z, pf[0].w, hp[1], lp[1]);
        split_pack(pf[1].x, pf[1].y, hp[2], lp[2]);
        split_pack(pf[1].z, pf[1].w, hp[3], lp[3]);
        split_pack(pf[2].x, pf[2].y, hp[4], lp[4]);
        split_pack(pf[2].z, pf[2].w, hp[5], lp[5]);
        split_pack(pf[3].x, pf[3].y, hp[6], lp[6]);
        split_pack(pf[3].z, pf[3].w, hp[7], lp[7]);
        uint32_t dst = smem_b + (uint32_t)(s * STAGE_B + ld_row * RSTRIDE + ld_kh * 32);
        sts128(dst,          hp[0], hp[1], hp[2], hp[3]);
        sts128(dst + 16,     hp[4], hp[5], hp[6], hp[7]);
        sts128(dst + PLANE,      lp[0], lp[1], lp[2], lp[3]);
        sts128(dst + PLANE + 16, lp[4], lp[5], lp[6], lp[7]);
    };
    auto cpB = [&](int c, int s) {
        uint32_t dst = smem_b + (uint32_t)(s * STAGE_B + 2 * PLANE +
                                           ld_row * RSTRIDE + ld_kh * 32);
        const uint32_t* sh = &g_Bh[(n0 + ld_row) * 128 + c * 16 + ld_kh * 8];
        const uint32_t* sl = &g_Bl[(n0 + ld_row) * 128 + c * 16 + ld_kh * 8];
        cp16(dst,              sh);
        cp16(dst + 16,         sh + 4);
        cp16(dst + PLANE,      sl);
        cp16(dst + PLANE + 16, sl + 4);
        asm volatile("cp.async.commit_group;" ::: "memory");
    };

    // prologue: fill stage 0
    ldgA(0);
    stsA(0);
    cpB(0, 0);

    for (int c = 0; c < NCHUNK; ++c) {
        const int s = c & 1;
        asm volatile("cp.async.wait_group 0;" ::: "memory");
        __syncthreads();   // stage s fully populated; stage s^1 free

        if (c + 1 < NCHUNK) {
            ldgA(c + 1);           // global latency hidden under compute
            cpB(c + 1, s ^ 1);
        }

        const uint32_t abase = smem_b + (uint32_t)(s * STAGE_B);
        const uint32_t bbase = abase + 2 * PLANE;

        #pragma unroll
        for (int kg = 0; kg < 2; ++kg) {
            const uint32_t ka = abase + kg * 32 + a_lane;
            // A fragments: hi + lo, both M tiles (4x LDSM.x4)
            uint4 Ah[2], Al[2];
            #pragma unroll
            for (int mt = 0; mt < 2; ++mt) {
                Ah[mt] = ldsm4(ka + mt * (16 * RSTRIDE));
                Al[mt] = ldsm4(ka + mt * (16 * RSTRIDE) + PLANE);
            }

            #pragma unroll
            for (int half = 0; half < 2; ++half) {
                // B: 2 nt-pairs (4 nt), hi + lo (4x LDSM.x4)
                uint4 Bh[2], Bl[2];
                #pragma unroll
                for (int p = 0; p < 2; ++p) {
                    uint32_t kb = bbase + kg * 32 + b_lane +
                                  (uint32_t)((half * 2 + p) * 16 * RSTRIDE);
                    Bh[p] = ldsm4(kb);
                    Bl[p] = ldsm4(kb + PLANE);
                }
                // term-major: acc-reuse distance 8
                #pragma unroll
                for (int p = 0; p < 2; ++p) {
                    const int nt = half * 4 + p * 2;
                    #pragma unroll
                    for (int mt = 0; mt < 2; ++mt) {
                        mma_bf16(acc[mt][nt],     Ah[mt].x, Ah[mt].y, Ah[mt].z, Ah[mt].w,
                                 Bh[p].x, Bh[p].y);
                        mma_bf16(acc[mt][nt + 1], Ah[mt].x, Ah[mt].y, Ah[mt].z, Ah[mt].w,
                                 Bh[p].z, Bh[p].w);
                    }
                }
                #pragma unroll
                for (int p = 0; p < 2; ++p) {
                    const int nt = half * 4 + p * 2;
                    #pragma unroll
                    for (int mt = 0; mt < 2; ++mt) {
                        mma_bf16(acc[mt][nt],     Ah[mt].x, Ah[mt].y, Ah[mt].z, Ah[mt].w,
                                 Bl[p].x, Bl[p].y);
                        mma_bf16(acc[mt][nt + 1], Ah[mt].x, Ah[mt].y, Ah[mt].z, Ah[mt].w,
                                 Bl[p].z, Bl[p].w);
                    }
                }
                #pragma unroll
                for (int p = 0; p < 2; ++p) {
                    const int nt = half * 4 + p * 2;
                    #pragma unroll
                    for (int mt = 0; mt < 2; ++mt) {
                        mma_bf16(acc[mt][nt],     Al[mt].x, Al[mt].y, Al[mt].z, Al[mt].w,
                                 Bh[p].x, Bh[p].y);
                        mma_bf16(acc[mt][nt + 1], Al[mt].x, Al[mt].y, Al[mt].z, Al[mt].w,
                                 Bh[p].z, Bh[p].w);
                    }
                }
            }
        }

        if (c + 1 < NCHUNK)
            stsA(s ^ 1);   // stage s^1 is free (all warps passed this iter's sync)
    }

    // ---- epilogue: out = a*acc + (1-a)*h ----
    float a = res_alpha[0];
    a = fminf(fmaxf(a, 0.0f), 1.0f);
    const float ra = 1.0f - a;

    #pragma unroll
    for (int mt = 0; mt < 2; ++mt) {
        const int r0 = m0 + wm + mt * 16 + grp;
        #pragma unroll
        for (int nt = 0; nt < 8; ++nt) {
            const int cc = n0 + wn + nt * 8 + 2 * tig;
            {
                size_t gi = (size_t)r0 * NDIM + cc;
                float2 hv = *reinterpret_cast<const float2*>(&h[gi]);
                float2 o;
                o.x = fmaf(a, acc[mt][nt][0], ra * hv.x);
                o.y = fmaf(a, acc[mt][nt][1], ra * hv.y);
                *reinterpret_cast<float2*>(&out[gi]) = o;
            }
            {
                size_t gi = (size_t)(r0 + 8) * NDIM + cc;
                float2 hv = *reinterpret_cast<const float2*>(&h[gi]);
                float2 o;
                o.x = fmaf(a, acc[mt][nt][2], ra * hv.x);
                o.y = fmaf(a, acc[mt][nt][3], ra * hv.y);
                *reinterpret_cast<float2*>(&out[gi]) = o;
            }
        }
    }
}

extern "C" void kernel_launch(void* const* d_in, const int* in_sizes, int n_in,
                              void* d_out, int out_size) {
    const float* h         = (const float*)d_in[0];   // [8, 2048, 256]
    // d_in[1] = adj (unused)
    const float* W         = (const float*)d_in[2];   // [4, 256, 64]
    const float* res_alpha = (const float*)d_in[3];
    float* out             = (float*)d_out;

    const int M = in_sizes[0] / K_DIM;                // 16384

    prep_Bt<<<(NDIM * K_DIM / 2) / 256, 256>>>(W);

    const int smem_bytes = 2 * STAGE_B;               // 81920
    cudaFuncSetAttribute(gat_mma_gemm,
                         cudaFuncAttributeMaxDynamicSharedMemorySize, smem_bytes);
    dim3 grid(NDIM / BN, M / BM);                     // (2, 128)
    gat_mma_gemm<<<grid, THREADS, smem_bytes>>>(h, res_alpha, out);
}